// round 15
// baseline (speedup 1.0000x reference)
#include <cuda_runtime.h>
#include <cuda_fp16.h>
#include <math.h>
#include <stdint.h>

#define NB    16
#define CIN   512
#define NPIX  1024
#define HEADS 8
#define DIMH  64
#define HID   512
#define K3    1536   // 3*HID

// Scratch (allocation-free, device globals)
__device__ __half g_wn_qkv[K3 * CIN];
__device__ __half g_wn_out[CIN * HID];
__device__ __half g_xh[(size_t)NB * CIN * NPIX];          // fp16 x [b][ch][pix]
__device__ __half g_attn[(size_t)NB * HID * NPIX];
__device__ __half g_qn[(size_t)NB * HEADS * NPIX * DIMH];
__device__ __half g_kn[(size_t)NB * HEADS * NPIX * DIMH];
__device__ __half g_vn[(size_t)NB * HEADS * NPIX * DIMH];
__device__ __half g_km[HEADS * 4 * DIMH];
__device__ __half g_vm[HEADS * 4 * DIMH];

// ---------------------------------------------------------------------------
// helpers
// ---------------------------------------------------------------------------
__device__ __forceinline__ float ex2f(float x) {
    float y;
    asm("ex2.approx.f32 %0, %1;" : "=f"(y) : "f"(x));
    return y;
}
__device__ __forceinline__ void mma_f16(float (&d)[4],
                                        uint32_t a0, uint32_t a1, uint32_t a2, uint32_t a3,
                                        uint32_t b0, uint32_t b1) {
    asm volatile(
        "mma.sync.aligned.m16n8k16.row.col.f32.f16.f16.f32 "
        "{%0,%1,%2,%3}, {%4,%5,%6,%7}, {%8,%9}, {%0,%1,%2,%3};"
        : "+f"(d[0]), "+f"(d[1]), "+f"(d[2]), "+f"(d[3])
        : "r"(a0), "r"(a1), "r"(a2), "r"(a3), "r"(b0), "r"(b1));
}
__device__ __forceinline__ void ldsm_x4(uint32_t& r0, uint32_t& r1, uint32_t& r2,
                                        uint32_t& r3, uint32_t addr) {
    asm volatile("ldmatrix.sync.aligned.m8n8.x4.shared.b16 {%0,%1,%2,%3}, [%4];"
                 : "=r"(r0), "=r"(r1), "=r"(r2), "=r"(r3) : "r"(addr));
}
__device__ __forceinline__ void ldsm_x4t(uint32_t& r0, uint32_t& r1, uint32_t& r2,
                                         uint32_t& r3, uint32_t addr) {
    asm volatile("ldmatrix.sync.aligned.m8n8.x4.trans.shared.b16 {%0,%1,%2,%3}, [%4];"
                 : "=r"(r0), "=r"(r1), "=r"(r2), "=r"(r3) : "r"(addr));
}
__device__ __forceinline__ void cp16(uint32_t s, const void* g) {
    asm volatile("cp.async.cg.shared.global [%0], [%1], 16;" :: "r"(s), "l"(g));
}
__device__ __forceinline__ void cp16z(uint32_t s, const void* g, int sz) {
    asm volatile("cp.async.cg.shared.global [%0], [%1], 16, %2;"
                 :: "r"(s), "l"(g), "r"(sz));
}
__device__ __forceinline__ uint32_t packh2(float a, float b) {
    __half2 h = __floats2half2_rn(a, b);
    return *(uint32_t*)&h;
}

// ---------------------------------------------------------------------------
// prep: weight norms (fan-in 512) + mem_kv norm + x fp32->fp16 (channel-major).
// ---------------------------------------------------------------------------
#define PREP_MEMKV (K3 + CIN)
#define PREP_X     (K3 + CIN + 64)

__global__ void __launch_bounds__(256) prep_kernel(const float* __restrict__ w_qkv,
                                                   const float* __restrict__ w_out,
                                                   const float* __restrict__ mem_kv,
                                                   const float* __restrict__ x,
                                                   __half* __restrict__ wnq,
                                                   __half* __restrict__ wno,
                                                   __half* __restrict__ km,
                                                   __half* __restrict__ vm,
                                                   __half* __restrict__ xh)
{
    int r = blockIdx.x;
    if (r >= PREP_X) {
        size_t base = (size_t)(r - PREP_X) * 4096;
#pragma unroll
        for (int j = 0; j < 2; j++) {
            size_t off = base + ((size_t)j * 256 + threadIdx.x) * 8;
            float4 f0 = *(const float4*)(x + off);
            float4 f1 = *(const float4*)(x + off + 4);
            uint4 pk;
            pk.x = packh2(f0.x, f0.y); pk.y = packh2(f0.z, f0.w);
            pk.z = packh2(f1.x, f1.y); pk.w = packh2(f1.z, f1.w);
            *(uint4*)(xh + off) = pk;
        }
        return;
    }
    if (r >= PREP_MEMKV) {
        if (threadIdx.x < 32) {
            int row = r - PREP_MEMKV;
            int part = row >> 5, rk = row & 31;
            const float* src = mem_kv + part * 2048 + rk * 64;
            float v0 = src[threadIdx.x], v1 = src[threadIdx.x + 32];
            float s = v0 * v0 + v1 * v1;
#pragma unroll
            for (int off = 16; off; off >>= 1) s += __shfl_xor_sync(0xffffffffu, s, off);
            float sc = 8.f / fmaxf(sqrtf(s), 1e-4f);
            __half* dst = (part ? vm : km) + rk * 64;
            dst[threadIdx.x]      = __float2half(v0 * sc);
            dst[threadIdx.x + 32] = __float2half(v1 * sc);
        }
        return;
    }
    const float* wr;
    __half* out;
    if (r < K3) { wr = w_qkv + (size_t)r * CIN;        out = wnq + (size_t)r * CIN; }
    else        { wr = w_out + (size_t)(r - K3) * HID; out = wno + (size_t)(r - K3) * HID; }
    float s = 0.f;
    for (int i = threadIdx.x; i < 512; i += 256) { float v = wr[i]; s += v * v; }
    __shared__ float red[8];
#pragma unroll
    for (int off = 16; off; off >>= 1) s += __shfl_xor_sync(0xffffffffu, s, off);
    if ((threadIdx.x & 31) == 0) red[threadIdx.x >> 5] = s;
    __syncthreads();
    if (threadIdx.x == 0) {
        float v = 0.f;
#pragma unroll
        for (int i = 0; i < 8; i++) v += red[i];
        red[0] = v;
    }
    __syncthreads();
    float inv = 1.f / (1e-4f * 22.627416998f + sqrtf(red[0]));
    for (int i = threadIdx.x; i < 512; i += 256)
        out[i] = __float2half(wr[i] * inv);
}

// ---------------------------------------------------------------------------
// WIDE fp16 GEMM, 512 threads: block 128(ch) x 256(pix), 16 warps (2m x 8n),
// warp tile 64x32 (identical per-warp shape to R10). 3-stage cp.async
// (A 16KB + B 32KB per stage = 144KB total), ONE sync per k-slab, 1 block/SM.
// QKV=true : fused pixel-norm epilogue -> qn/kn/vn. QKV=false: MPAdd -> fp32.
// ---------------------------------------------------------------------------
template<int MD, bool QKV>
__global__ void __launch_bounds__(512, 1) hgemm_w512(const __half* __restrict__ A,
                                                     const __half* __restrict__ Bm,
                                                     __half* __restrict__ qn,
                                                     __half* __restrict__ kn,
                                                     __half* __restrict__ vn,
                                                     float* __restrict__ Cf,
                                                     const float* __restrict__ X)
{
    constexpr int ND = 1024, KD = 512;
    extern __shared__ char smc[];
    const uint32_t sb = (uint32_t)__cvta_generic_to_shared(smc);
    constexpr uint32_t STAGE = 49152;   // 16KB A + 32KB B

    const int b   = blockIdx.z;
    const int bm0 = blockIdx.y * 128;   // channel tile
    const int bn0 = blockIdx.x * 256;   // pixel tile
    const __half* Bh = Bm + (size_t)b * KD * ND;

    const int tid = threadIdx.x;
    const int w = tid >> 5, lane = tid & 31;
    const int g = lane >> 2, tg = lane & 3;
    const int mat = lane >> 3, rr = lane & 7;
    const int m_off = (w >> 3) * 64;    // 0 or 64   (channel)
    const int n_off = (w & 7) * 32;     // 0..224    (pixel)

    float acc[4][4][4];
#pragma unroll
    for (int i = 0; i < 4; i++)
#pragma unroll
        for (int j = 0; j < 4; j++)
#pragma unroll
            for (int r = 0; r < 4; r++) acc[i][j][r] = 0.f;

    // staging: A 1024 chunks (128r x 8c, rows 128B), B 2048 chunks (64r x 32c, rows 512B)
    int ar[2], ac[2];
    uint32_t aoff[2];
#pragma unroll
    for (int i = 0; i < 2; i++) {
        int cid = i * 512 + tid;
        ar[i] = cid >> 3;  ac[i] = cid & 7;
        aoff[i] = ar[i] * 128 + ((ac[i] ^ (ar[i] & 7)) << 4);
    }
    int br_[4], bc[4];
    uint32_t boff[4];
#pragma unroll
    for (int i = 0; i < 4; i++) {
        int cid = i * 512 + tid;
        br_[i] = cid >> 5;  bc[i] = cid & 31;
        boff[i] = 16384 + br_[i] * 512 +
                  (((bc[i] & 24) | ((bc[i] & 7) ^ (br_[i] & 7))) << 4);
    }

    // prologue: slabs 0,1 into stages 0,1
#pragma unroll
    for (int s = 0; s < 2; s++) {
        int k0 = s * 64;
        uint32_t st = sb + s * STAGE;
#pragma unroll
        for (int i = 0; i < 2; i++)
            cp16(st + aoff[i], A + (size_t)(bm0 + ar[i]) * KD + k0 + ac[i] * 8);
#pragma unroll
        for (int i = 0; i < 4; i++)
            cp16(st + boff[i], Bh + (size_t)(k0 + br_[i]) * ND + bn0 + bc[i] * 8);
        asm volatile("cp.async.commit_group;");
    }

    int s_comp = 0, s_issue = 2;
    for (int it = 0; it < 8; ++it) {
        if (it < 7) asm volatile("cp.async.wait_group 1;");
        else        asm volatile("cp.async.wait_group 0;");
        __syncthreads();   // slab it visible; stage s_issue's old contents consumed

        if (it + 2 < 8) {
            int k0 = (it + 2) * 64;
            uint32_t st = sb + s_issue * STAGE;
#pragma unroll
            for (int i = 0; i < 2; i++)
                cp16(st + aoff[i], A + (size_t)(bm0 + ar[i]) * KD + k0 + ac[i] * 8);
#pragma unroll
            for (int i = 0; i < 4; i++)
                cp16(st + boff[i], Bh + (size_t)(k0 + br_[i]) * ND + bn0 + bc[i] * 8);
            asm volatile("cp.async.commit_group;");
            s_issue++; if (s_issue == 3) s_issue = 0;
        }

        const uint32_t AS = sb + s_comp * STAGE;
        const uint32_t BS = AS + 16384;
        s_comp++; if (s_comp == 3) s_comp = 0;
#pragma unroll
        for (int kk = 0; kk < 4; kk++) {
            uint32_t af[4][4];
#pragma unroll
            for (int mt = 0; mt < 4; mt++) {
                int row = m_off + mt * 16 + (mat & 1) * 8 + rr;
                int ch = kk * 2 + (mat >> 1);
                ldsm_x4(af[mt][0], af[mt][1], af[mt][2], af[mt][3],
                        AS + row * 128 + ((ch ^ (row & 7)) << 4));
            }
#pragma unroll
            for (int np = 0; np < 2; np++) {
                int row = kk * 16 + (mat & 1) * 8 + rr;
                int c = (n_off >> 3) + np * 2 + (mat >> 1);
                uint32_t b0, b1, b2, b3;
                ldsm_x4t(b0, b1, b2, b3,
                         BS + row * 512 + (((c & 24) | ((c & 7) ^ (row & 7))) << 4));
#pragma unroll
                for (int mt = 0; mt < 4; mt++) {
                    mma_f16(acc[mt][np * 2],     af[mt][0], af[mt][1], af[mt][2], af[mt][3], b0, b1);
                    mma_f16(acc[mt][np * 2 + 1], af[mt][0], af[mt][1], af[mt][2], af[mt][3], b2, b3);
                }
            }
        }
    }

    if (QKV) {
        // fused pixel-norm epilogue (R10 per-warp shape); staging 16 x 4KB = 64KB
        __syncthreads();
        const int gr0  = bm0 + m_off;
        const int comp = gr0 >> 9;
        const int head = (gr0 & 511) >> 6;
        const float sc_num = (comp == 0) ? 1.4426950408889634f : 8.f;
        __half* st = (__half*)(smc + w * 4096); // warp-private [col 0..31][d 0..63]

#pragma unroll
        for (int nt = 0; nt < 4; nt++) {
            float ss0 = 0.f, ss1 = 0.f;
#pragma unroll
            for (int mt = 0; mt < 4; mt++) {
                ss0 += acc[mt][nt][0] * acc[mt][nt][0] + acc[mt][nt][2] * acc[mt][nt][2];
                ss1 += acc[mt][nt][1] * acc[mt][nt][1] + acc[mt][nt][3] * acc[mt][nt][3];
            }
#pragma unroll
            for (int off = 4; off <= 16; off <<= 1) {
                ss0 += __shfl_xor_sync(0xffffffffu, ss0, off);
                ss1 += __shfl_xor_sync(0xffffffffu, ss1, off);
            }
            float s0 = sc_num / fmaxf(sqrtf(ss0), 1e-4f);
            float s1 = sc_num / fmaxf(sqrtf(ss1), 1e-4f);
            int c0 = nt * 8 + 2 * tg;
#pragma unroll
            for (int mt = 0; mt < 4; mt++) {
                int r = mt * 16 + g;
                st[c0 * 64 + r]           = __float2half(acc[mt][nt][0] * s0);
                st[c0 * 64 + r + 8]       = __float2half(acc[mt][nt][2] * s0);
                st[(c0 + 1) * 64 + r]     = __float2half(acc[mt][nt][1] * s1);
                st[(c0 + 1) * 64 + r + 8] = __float2half(acc[mt][nt][3] * s1);
            }
        }
        __syncwarp();
        __half* dst = (comp == 0 ? qn : comp == 1 ? kn : vn) +
                      ((size_t)(b * HEADS + head) * NPIX + bn0 + n_off) * DIMH;
#pragma unroll 8
        for (int c = 0; c < 32; c++) {
            __half2 v = *(__half2*)(st + c * 64 + lane * 2);
            *(__half2*)(dst + (size_t)c * DIMH + lane * 2) = v;
        }
    } else {
        const float a_out = 0.9191450300f;  // 0.7 / sqrt(0.58)
        const float a_x   = 0.3939192986f;  // 0.3 / sqrt(0.58)
        float* Cb = Cf + (size_t)b * MD * ND;
#pragma unroll
        for (int mt = 0; mt < 4; mt++) {
            int r1 = bm0 + m_off + mt * 16 + g;
            int r2 = r1 + 8;
#pragma unroll
            for (int nt = 0; nt < 4; nt++) {
                int col = bn0 + n_off + nt * 8 + 2 * tg;
                float2 v1 = make_float2(acc[mt][nt][0], acc[mt][nt][1]);
                float2 v2 = make_float2(acc[mt][nt][2], acc[mt][nt][3]);
                float2 x1 = *(const float2*)&X[((size_t)b * MD + r1) * ND + col];
                float2 x2 = *(const float2*)&X[((size_t)b * MD + r2) * ND + col];
                v1.x = v1.x * a_out + x1.x * a_x;  v1.y = v1.y * a_out + x1.y * a_x;
                v2.x = v2.x * a_out + x2.x * a_x;  v2.y = v2.y * a_out + x2.y * a_x;
                *(float2*)&Cb[(size_t)r1 * ND + col] = v1;
                *(float2*)&Cb[(size_t)r2 * ND + col] = v2;
            }
        }
    }
}

// ---------------------------------------------------------------------------
// fp16 flash attention, 128-query blocks, 3-stage cp.async K/V,
// register-direct P (validated R14). smem 64KB.
// ---------------------------------------------------------------------------
__global__ void __launch_bounds__(256, 2) attn_f16(const __half* __restrict__ qn,
                                                   const __half* __restrict__ kn,
                                                   const __half* __restrict__ vn,
                                                   const __half* __restrict__ km,
                                                   const __half* __restrict__ vm,
                                                   __half* __restrict__ attn_out)
{
    extern __shared__ char smc[];
    const uint32_t sb = (uint32_t)__cvta_generic_to_shared(smc);
    const uint32_t QS = sb, KS = sb + 16384, VS = sb + 40960;

    const int b = blockIdx.z, h = blockIdx.y, i0 = blockIdx.x * 128;
    const int tid = threadIdx.x, lane = tid & 31;
    const int g = lane >> 2, tg = lane & 3;
    const int m0 = (tid >> 5) * 16;
    const int mat = lane >> 3, rr = lane & 7;

    const __half* qh = qn + ((size_t)(b * HEADS + h) * NPIX + i0) * DIMH;
    const __half* kh = kn + (size_t)(b * HEADS + h) * NPIX * DIMH;
    const __half* vh = vn + (size_t)(b * HEADS + h) * NPIX * DIMH;

    int cr[2], cc[2];
    uint32_t coff[2];
#pragma unroll
    for (int i = 0; i < 2; i++) {
        int idx = tid + i * 256;
        cr[i] = idx >> 3;  cc[i] = idx & 7;
        coff[i] = cr[i] * 128 + ((cc[i] ^ (cr[i] & 7)) << 4);
    }

#pragma unroll
    for (int i = 0; i < 2; i++) {
        int sz = (cr[i] < 4) ? 16 : 0;
        cp16z(KS + coff[i], km + ((h * 4 + (cr[i] & 3)) * 64 + cc[i] * 8), sz);
        cp16z(VS + coff[i], vm + ((h * 4 + (cr[i] & 3)) * 64 + cc[i] * 8), sz);
    }
    asm volatile("cp.async.commit_group;");
#pragma unroll
    for (int i = 0; i < 2; i++) {
        cp16(KS + 8192 + coff[i], kh + cr[i] * 64 + cc[i] * 8);
        cp16(VS + 8192 + coff[i], vh + cr[i] * 64 + cc[i] * 8);
    }
    asm volatile("cp.async.commit_group;");

    for (int idx = tid; idx < 1024; idx += 256) {
        int r = idx >> 3, c = idx & 7;
        uint4 v = *(const uint4*)(qh + r * 64 + c * 8);
        *(uint4*)(smc + r * 128 + ((c ^ (r & 7)) << 4)) = v;
    }
    __syncthreads();

    uint32_t aq[4][4];
    {
        int qrow = m0 + (mat & 1) * 8 + rr;
#pragma unroll
        for (int kc = 0; kc < 4; kc++) {
            int ch = 2 * kc + (mat >> 1);
            ldsm_x4(aq[kc][0], aq[kc][1], aq[kc][2], aq[kc][3],
                    QS + qrow * 128 + ((ch ^ (qrow & 7)) << 4));
        }
    }

    float oacc[8][4];
#pragma unroll
    for (int nt = 0; nt < 8; nt++)
#pragma unroll
        for (int r = 0; r < 4; r++) oacc[nt][r] = 0.f;
    float mrow[2] = {-1e30f, -1e30f};
    float lrow[2] = {0.f, 0.f};

    int s_comp = 0, s_issue = 2;
    for (int t = 0; t <= 16; ++t) {
        if (t < 16) asm volatile("cp.async.wait_group 1;");
        else        asm volatile("cp.async.wait_group 0;");
        __syncthreads();

        if (t + 2 <= 16) {
            const __half* kt = kh + (size_t)(t + 1) * 64 * 64;
            const __half* vt = vh + (size_t)(t + 1) * 64 * 64;
            uint32_t kb = KS + s_issue * 8192;
            uint32_t vb = VS + s_issue * 8192;
#pragma unroll
            for (int i = 0; i < 2; i++) {
                cp16(kb + coff[i], kt + cr[i] * 64 + cc[i] * 8);
                cp16(vb + coff[i], vt + cr[i] * 64 + cc[i] * 8);
            }
            asm volatile("cp.async.commit_group;");
            s_issue++; if (s_issue == 3) s_issue = 0;
        }

        const uint32_t kb = KS + s_comp * 8192;
        const uint32_t vb = VS + s_comp * 8192;
        s_comp++; if (s_comp == 3) s_comp = 0;

        float sacc[8][4];
#pragma unroll
        for (int nt = 0; nt < 8; nt++)
#pragma unroll
            for (int r = 0; r < 4; r++) sacc[nt][r] = 0.f;
#pragma unroll
        for (int np = 0; np < 4; np++) {
            int key = (2 * np + (mat >> 1)) * 8 + rr;
#pragma unroll
            for (int kc = 0; kc < 4; kc++) {
                int ch = 2 * kc + (mat & 1);
                uint32_t addr = kb + key * 128 + ((ch ^ (key & 7)) << 4);
                uint32_t b0, b1, b2, b3;
                ldsm_x4(b0, b1, b2, b3, addr);
                mma_f16(sacc[2 * np],     aq[kc][0], aq[kc][1], aq[kc][2], aq[kc][3], b0, b1);
                mma_f16(sacc[2 * np + 1], aq[kc][0], aq[kc][1], aq[kc][2], aq[kc][3], b2, b3);
            }
        }
        if (t == 0) {
#pragma unroll
            for (int nt = 0; nt < 8; nt++) {
                int c0 = nt * 8 + 2 * tg;
                if (c0 >= 4)     { sacc[nt][0] = -1e30f; sacc[nt][2] = -1e30f; }
                if (c0 + 1 >= 4) { sacc[nt][1] = -1e30f; sacc[nt][3] = -1e30f; }
            }
        }

        float tm0 = -1e30f, tm1 = -1e30f;
#pragma unroll
        for (int nt = 0; nt < 8; nt++) {
            tm0 = fmaxf(tm0, fmaxf(sacc[nt][0], sacc[nt][1]));
            tm1 = fmaxf(tm1, fmaxf(sacc[nt][2], sacc[nt][3]));
        }
        tm0 = fmaxf(tm0, __shfl_xor_sync(0xffffffffu, tm0, 1));
        tm0 = fmaxf(tm0, __shfl_xor_sync(0xffffffffu, tm0, 2));
        tm1 = fmaxf(tm1, __shfl_xor_sync(0xffffffffu, tm1, 1));
        tm1 = fmaxf(tm1, __shfl_xor_sync(0xffffffffu, tm1, 2));

        float mn0 = fmaxf(mrow[0], tm0), mn1 = fmaxf(mrow[1], tm1);
        float al0 = ex2f(mrow[0] - mn0), al1 = ex2f(mrow[1] - mn1);
        float rs0 = 0.f, rs1 = 0.f;
        uint32_t pa[8], pb[8];
#pragma unroll
        for (int nt = 0; nt < 8; nt++) {
            float p00 = ex2f(sacc[nt][0] - mn0);
            float p01 = ex2f(sacc[nt][1] - mn0);
            float p10 = ex2f(sacc[nt][2] - mn1);
            float p11 = ex2f(sacc[nt][3] - mn1);
            rs0 += p00 + p01;  rs1 += p10 + p11;
            pa[nt] = packh2(p00, p01);
            pb[nt] = packh2(p10, p11);
        }
        rs0 += __shfl_xor_sync(0xffffffffu, rs0, 1);
        rs0 += __shfl_xor_sync(0xffffffffu, rs0, 2);
        rs1 += __shfl_xor_sync(0xffffffffu, rs1, 1);
        rs1 += __shfl_xor_sync(0xffffffffu, rs1, 2);
        lrow[0] = lrow[0] * al0 + rs0;  mrow[0] = mn0;
        lrow[1] = lrow[1] * al1 + rs1;  mrow[1] = mn1;
#pragma unroll
        for (int nt = 0; nt < 8; nt++) {
            oacc[nt][0] *= al0;  oacc[nt][1] *= al0;
            oacc[nt][2] *= al1;  oacc[nt][3] *= al1;
        }

#pragma unroll
        for (int kc = 0; kc < 4; kc++) {
            uint32_t a0 = pa[2 * kc],     a1 = pb[2 * kc];
            uint32_t a2 = pa[2 * kc + 1], a3 = pb[2 * kc + 1];
            int key = kc * 16 + (mat & 1) * 8 + rr;
#pragma unroll
            for (int np = 0; np < 4; np++) {
                int ch = 2 * np + (mat >> 1);
                uint32_t vaddr = vb + key * 128 + ((ch ^ (key & 7)) << 4);
                uint32_t b0, b1, b2, b3;
                ldsm_x4t(b0, b1, b2, b3, vaddr);
                mma_f16(oacc[2 * np],     a0, a1, a2, a3, b0, b1);
                mma_f16(oacc[2 * np + 1], a0, a1, a2, a3, b2, b3);
            }
        }
    }

    __syncthreads();
    float* fs = (float*)smc;
    {
        float il0 = 1.f / lrow[0], il1 = 1.f / lrow[1];
        const int row0 = m0 + g, row1 = m0 + g + 8;
#pragma unroll
        for (int nt = 0; nt < 8; nt++) {
            int c = nt * 8 + 2 * tg;
            fs[row0 * 66 + c]     = oacc[nt][0] * il0;
            fs[row0 * 66 + c + 1] = oacc[nt][1] * il0;
            fs[row1 * 66 + c]     = oacc[nt][2] * il1;
            fs[row1 * 66 + c + 1] = oacc[nt][3] * il1;
        }
    }
    __syncthreads();
    {
        __half* ob = attn_out + ((size_t)b * HID + h * DIMH) * NPIX;
        for (int idx = tid; idx < 128 * 64; idx += 256) {
            int m = idx & 127, d = idx >> 7;
            ob[(size_t)d * NPIX + i0 + m] = __float2half(fs[m * 66 + d]);
        }
    }
}

// ---------------------------------------------------------------------------
extern "C" void kernel_launch(void* const* d_in, const int* in_sizes, int n_in,
                              void* d_out, int out_size)
{
    const float* x      = (const float*)d_in[0];  // [16,512,32,32]
    const float* w_qkv  = (const float*)d_in[1];  // [1536,512]
    const float* w_out  = (const float*)d_in[2];  // [512,512]
    const float* mem_kv = (const float*)d_in[3];  // [2,8,4,64]
    float* out = (float*)d_out;                   // [16,512,32,32]

    __half *wnq, *wno, *xh, *attn, *qn, *kn, *vn, *km, *vm;
    cudaGetSymbolAddress((void**)&wnq,  g_wn_qkv);
    cudaGetSymbolAddress((void**)&wno,  g_wn_out);
    cudaGetSymbolAddress((void**)&xh,   g_xh);
    cudaGetSymbolAddress((void**)&attn, g_attn);
    cudaGetSymbolAddress((void**)&qn,   g_qn);
    cudaGetSymbolAddress((void**)&kn,   g_kn);
    cudaGetSymbolAddress((void**)&vn,   g_vn);
    cudaGetSymbolAddress((void**)&km,   g_km);
    cudaGetSymbolAddress((void**)&vm,   g_vm);

    const int gsm = 3 * 49152;   // 147456
    cudaFuncSetAttribute(hgemm_w512<K3, true>,
                         cudaFuncAttributeMaxDynamicSharedMemorySize, gsm);
    cudaFuncSetAttribute(hgemm_w512<CIN, false>,
                         cudaFuncAttributeMaxDynamicSharedMemorySize, gsm);
    cudaFuncSetAttribute(attn_f16, cudaFuncAttributeMaxDynamicSharedMemorySize, 65536);

    // prep: weight norms + mem_kv norm + x->fp16
    prep_kernel<<<PREP_X + 2048, 256>>>(w_qkv, w_out, mem_kv, x,
                                        wnq, wno, km, vm, xh);

    // QKV projection with fused pixel-norm (wide 512-thread tile)
    hgemm_w512<K3, true><<<dim3(4, K3 / 128, NB), 512, gsm>>>(
        wnq, xh, qn, kn, vn, nullptr, nullptr);

    // Attention (register-direct P)
    attn_f16<<<dim3(NPIX / 128, HEADS, NB), 256, 65536>>>(qn, kn, vn, km, vm, attn);

    // Output projection + MPAdd residual (wide 512-thread tile)
    hgemm_w512<CIN, false><<<dim3(4, CIN / 128, NB), 512, gsm>>>(
        wno, attn, nullptr, nullptr, nullptr, out, x);
}

// round 16
// speedup vs baseline: 1.1250x; 1.1250x over previous
#include <cuda_runtime.h>
#include <cuda_fp16.h>
#include <math.h>
#include <stdint.h>

#define NB    16
#define CIN   512
#define NPIX  1024
#define HEADS 8
#define DIMH  64
#define HID   512
#define K3    1536   // 3*HID
#define NBH   8      // batches per pipeline half

// Scratch (allocation-free, device globals)
__device__ __half g_wn_qkv[K3 * CIN];
__device__ __half g_wn_out[CIN * HID];
__device__ __half g_xh[(size_t)NB * CIN * NPIX];          // fp16 x [b][ch][pix]
__device__ __half g_attn[(size_t)NB * HID * NPIX];
__device__ __half g_qn[(size_t)NB * HEADS * NPIX * DIMH];
__device__ __half g_kn[(size_t)NB * HEADS * NPIX * DIMH];
__device__ __half g_vn[(size_t)NB * HEADS * NPIX * DIMH];
__device__ __half g_km[HEADS * 4 * DIMH];
__device__ __half g_vm[HEADS * 4 * DIMH];

// ---------------------------------------------------------------------------
// helpers
// ---------------------------------------------------------------------------
__device__ __forceinline__ float ex2f(float x) {
    float y;
    asm("ex2.approx.f32 %0, %1;" : "=f"(y) : "f"(x));
    return y;
}
__device__ __forceinline__ void mma_f16(float (&d)[4],
                                        uint32_t a0, uint32_t a1, uint32_t a2, uint32_t a3,
                                        uint32_t b0, uint32_t b1) {
    asm volatile(
        "mma.sync.aligned.m16n8k16.row.col.f32.f16.f16.f32 "
        "{%0,%1,%2,%3}, {%4,%5,%6,%7}, {%8,%9}, {%0,%1,%2,%3};"
        : "+f"(d[0]), "+f"(d[1]), "+f"(d[2]), "+f"(d[3])
        : "r"(a0), "r"(a1), "r"(a2), "r"(a3), "r"(b0), "r"(b1));
}
__device__ __forceinline__ void ldsm_x4(uint32_t& r0, uint32_t& r1, uint32_t& r2,
                                        uint32_t& r3, uint32_t addr) {
    asm volatile("ldmatrix.sync.aligned.m8n8.x4.shared.b16 {%0,%1,%2,%3}, [%4];"
                 : "=r"(r0), "=r"(r1), "=r"(r2), "=r"(r3) : "r"(addr));
}
__device__ __forceinline__ void ldsm_x4t(uint32_t& r0, uint32_t& r1, uint32_t& r2,
                                         uint32_t& r3, uint32_t addr) {
    asm volatile("ldmatrix.sync.aligned.m8n8.x4.trans.shared.b16 {%0,%1,%2,%3}, [%4];"
                 : "=r"(r0), "=r"(r1), "=r"(r2), "=r"(r3) : "r"(addr));
}
__device__ __forceinline__ void cp16(uint32_t s, const void* g) {
    asm volatile("cp.async.cg.shared.global [%0], [%1], 16;" :: "r"(s), "l"(g));
}
__device__ __forceinline__ void cp16z(uint32_t s, const void* g, int sz) {
    asm volatile("cp.async.cg.shared.global [%0], [%1], 16, %2;"
                 :: "r"(s), "l"(g), "r"(sz));
}
__device__ __forceinline__ uint32_t packh2(float a, float b) {
    __half2 h = __floats2half2_rn(a, b);
    return *(uint32_t*)&h;
}

// ---------------------------------------------------------------------------
// prep: weight norms (fan-in 512) + mem_kv norm + x fp32->fp16 (channel-major).
// ---------------------------------------------------------------------------
#define PREP_MEMKV (K3 + CIN)
#define PREP_X     (K3 + CIN + 64)

__global__ void __launch_bounds__(256) prep_kernel(const float* __restrict__ w_qkv,
                                                   const float* __restrict__ w_out,
                                                   const float* __restrict__ mem_kv,
                                                   const float* __restrict__ x,
                                                   __half* __restrict__ wnq,
                                                   __half* __restrict__ wno,
                                                   __half* __restrict__ km,
                                                   __half* __restrict__ vm,
                                                   __half* __restrict__ xh)
{
    int r = blockIdx.x;
    if (r >= PREP_X) {
        size_t base = (size_t)(r - PREP_X) * 4096;
#pragma unroll
        for (int j = 0; j < 2; j++) {
            size_t off = base + ((size_t)j * 256 + threadIdx.x) * 8;
            float4 f0 = *(const float4*)(x + off);
            float4 f1 = *(const float4*)(x + off + 4);
            uint4 pk;
            pk.x = packh2(f0.x, f0.y); pk.y = packh2(f0.z, f0.w);
            pk.z = packh2(f1.x, f1.y); pk.w = packh2(f1.z, f1.w);
            *(uint4*)(xh + off) = pk;
        }
        return;
    }
    if (r >= PREP_MEMKV) {
        if (threadIdx.x < 32) {
            int row = r - PREP_MEMKV;
            int part = row >> 5, rk = row & 31;
            const float* src = mem_kv + part * 2048 + rk * 64;
            float v0 = src[threadIdx.x], v1 = src[threadIdx.x + 32];
            float s = v0 * v0 + v1 * v1;
#pragma unroll
            for (int off = 16; off; off >>= 1) s += __shfl_xor_sync(0xffffffffu, s, off);
            float sc = 8.f / fmaxf(sqrtf(s), 1e-4f);
            __half* dst = (part ? vm : km) + rk * 64;
            dst[threadIdx.x]      = __float2half(v0 * sc);
            dst[threadIdx.x + 32] = __float2half(v1 * sc);
        }
        return;
    }
    const float* wr;
    __half* out;
    if (r < K3) { wr = w_qkv + (size_t)r * CIN;        out = wnq + (size_t)r * CIN; }
    else        { wr = w_out + (size_t)(r - K3) * HID; out = wno + (size_t)(r - K3) * HID; }
    float s = 0.f;
    for (int i = threadIdx.x; i < 512; i += 256) { float v = wr[i]; s += v * v; }
    __shared__ float red[8];
#pragma unroll
    for (int off = 16; off; off >>= 1) s += __shfl_xor_sync(0xffffffffu, s, off);
    if ((threadIdx.x & 31) == 0) red[threadIdx.x >> 5] = s;
    __syncthreads();
    if (threadIdx.x == 0) {
        float v = 0.f;
#pragma unroll
        for (int i = 0; i < 8; i++) v += red[i];
        red[0] = v;
    }
    __syncthreads();
    float inv = 1.f / (1e-4f * 22.627416998f + sqrtf(red[0]));
    for (int i = threadIdx.x; i < 512; i += 256)
        out[i] = __float2half(wr[i] * inv);
}

// ---------------------------------------------------------------------------
// 3-stage cp.async fp16 GEMM (validated R10/R14): C[b](MDx1024)=A(MDx512)*B[b].
// QKV=true : fused pixel-norm epilogue -> qn/kn/vn. QKV=false: MPAdd -> fp32.
// ---------------------------------------------------------------------------
template<int MD, bool QKV>
__global__ void __launch_bounds__(256, 2) hgemm_pipe(const __half* __restrict__ A,
                                                     const __half* __restrict__ Bm,
                                                     __half* __restrict__ qn,
                                                     __half* __restrict__ kn,
                                                     __half* __restrict__ vn,
                                                     float* __restrict__ Cf,
                                                     const float* __restrict__ X)
{
    constexpr int ND = 1024, KD = 512;
    extern __shared__ char smc[];
    const uint32_t sb = (uint32_t)__cvta_generic_to_shared(smc);

    const int b   = blockIdx.z;
    const int bm0 = blockIdx.y * 128;
    const int bn0 = blockIdx.x * 128;
    const __half* Bh = Bm + (size_t)b * KD * ND;

    const int tid = threadIdx.x;
    const int w = tid >> 5, lane = tid & 31;
    const int g = lane >> 2, tg = lane & 3;
    const int mat = lane >> 3, rr = lane & 7;
    const int m_off = (w >> 2) * 64;
    const int n_off = (w & 3) * 32;

    float acc[4][4][4];
#pragma unroll
    for (int i = 0; i < 4; i++)
#pragma unroll
        for (int j = 0; j < 4; j++)
#pragma unroll
            for (int r = 0; r < 4; r++) acc[i][j][r] = 0.f;

    int ar[4], ac[4], br_[4], bc[4];
    uint32_t aoff[4], boff[4];
#pragma unroll
    for (int i = 0; i < 4; i++) {
        int cid = i * 256 + tid;
        ar[i] = cid >> 3;  ac[i] = cid & 7;
        br_[i] = cid >> 4; bc[i] = cid & 15;
        aoff[i] = ar[i] * 128 + ((ac[i] ^ (ar[i] & 7)) << 4);
        boff[i] = 16384 + br_[i] * 256 +
                  (((bc[i] & 8) | ((bc[i] & 7) ^ (br_[i] & 7))) << 4);
    }

#pragma unroll
    for (int s = 0; s < 2; s++) {
        int k0 = s * 64;
        uint32_t st = sb + s * 32768;
#pragma unroll
        for (int i = 0; i < 4; i++) {
            cp16(st + aoff[i], A + (size_t)(bm0 + ar[i]) * KD + k0 + ac[i] * 8);
            cp16(st + boff[i], Bh + (size_t)(k0 + br_[i]) * ND + bn0 + bc[i] * 8);
        }
        asm volatile("cp.async.commit_group;");
    }

    int s_comp = 0, s_issue = 2;
    for (int it = 0; it < 8; ++it) {
        if (it < 7) asm volatile("cp.async.wait_group 1;");
        else        asm volatile("cp.async.wait_group 0;");
        __syncthreads();

        if (it + 2 < 8) {
            int k0 = (it + 2) * 64;
            uint32_t st = sb + s_issue * 32768;
#pragma unroll
            for (int i = 0; i < 4; i++) {
                cp16(st + aoff[i], A + (size_t)(bm0 + ar[i]) * KD + k0 + ac[i] * 8);
                cp16(st + boff[i], Bh + (size_t)(k0 + br_[i]) * ND + bn0 + bc[i] * 8);
            }
            asm volatile("cp.async.commit_group;");
            s_issue++; if (s_issue == 3) s_issue = 0;
        }

        const uint32_t AS = sb + s_comp * 32768;
        const uint32_t BS = AS + 16384;
        s_comp++; if (s_comp == 3) s_comp = 0;
#pragma unroll
        for (int kk = 0; kk < 4; kk++) {
            uint32_t af[4][4];
#pragma unroll
            for (int mt = 0; mt < 4; mt++) {
                int row = m_off + mt * 16 + (mat & 1) * 8 + rr;
                int ch = kk * 2 + (mat >> 1);
                ldsm_x4(af[mt][0], af[mt][1], af[mt][2], af[mt][3],
                        AS + row * 128 + ((ch ^ (row & 7)) << 4));
            }
#pragma unroll
            for (int np = 0; np < 2; np++) {
                int row = kk * 16 + (mat & 1) * 8 + rr;
                int c = (n_off >> 3) + np * 2 + (mat >> 1);
                uint32_t b0, b1, b2, b3;
                ldsm_x4t(b0, b1, b2, b3,
                         BS + row * 256 + (((c & 8) | ((c & 7) ^ (row & 7))) << 4));
#pragma unroll
                for (int mt = 0; mt < 4; mt++) {
                    mma_f16(acc[mt][np * 2],     af[mt][0], af[mt][1], af[mt][2], af[mt][3], b0, b1);
                    mma_f16(acc[mt][np * 2 + 1], af[mt][0], af[mt][1], af[mt][2], af[mt][3], b2, b3);
                }
            }
        }
    }

    if (QKV) {
        __syncthreads();
        const int gr0  = bm0 + m_off;
        const int comp = gr0 >> 9;
        const int head = (gr0 & 511) >> 6;
        const float sc_num = (comp == 0) ? 1.4426950408889634f : 8.f;
        __half* st = (__half*)(smc + w * 4096);

#pragma unroll
        for (int nt = 0; nt < 4; nt++) {
            float ss0 = 0.f, ss1 = 0.f;
#pragma unroll
            for (int mt = 0; mt < 4; mt++) {
                ss0 += acc[mt][nt][0] * acc[mt][nt][0] + acc[mt][nt][2] * acc[mt][nt][2];
                ss1 += acc[mt][nt][1] * acc[mt][nt][1] + acc[mt][nt][3] * acc[mt][nt][3];
            }
#pragma unroll
            for (int off = 4; off <= 16; off <<= 1) {
                ss0 += __shfl_xor_sync(0xffffffffu, ss0, off);
                ss1 += __shfl_xor_sync(0xffffffffu, ss1, off);
            }
            float s0 = sc_num / fmaxf(sqrtf(ss0), 1e-4f);
            float s1 = sc_num / fmaxf(sqrtf(ss1), 1e-4f);
            int c0 = nt * 8 + 2 * tg;
#pragma unroll
            for (int mt = 0; mt < 4; mt++) {
                int r = mt * 16 + g;
                st[c0 * 64 + r]           = __float2half(acc[mt][nt][0] * s0);
                st[c0 * 64 + r + 8]       = __float2half(acc[mt][nt][2] * s0);
                st[(c0 + 1) * 64 + r]     = __float2half(acc[mt][nt][1] * s1);
                st[(c0 + 1) * 64 + r + 8] = __float2half(acc[mt][nt][3] * s1);
            }
        }
        __syncwarp();
        __half* dst = (comp == 0 ? qn : comp == 1 ? kn : vn) +
                      ((size_t)(b * HEADS + head) * NPIX + bn0 + n_off) * DIMH;
#pragma unroll 8
        for (int c = 0; c < 32; c++) {
            __half2 v = *(__half2*)(st + c * 64 + lane * 2);
            *(__half2*)(dst + (size_t)c * DIMH + lane * 2) = v;
        }
    } else {
        const float a_out = 0.9191450300f;  // 0.7 / sqrt(0.58)
        const float a_x   = 0.3939192986f;  // 0.3 / sqrt(0.58)
        float* Cb = Cf + (size_t)b * MD * ND;
#pragma unroll
        for (int mt = 0; mt < 4; mt++) {
            int r1 = bm0 + m_off + mt * 16 + g;
            int r2 = r1 + 8;
#pragma unroll
            for (int nt = 0; nt < 4; nt++) {
                int col = bn0 + n_off + nt * 8 + 2 * tg;
                float2 v1 = make_float2(acc[mt][nt][0], acc[mt][nt][1]);
                float2 v2 = make_float2(acc[mt][nt][2], acc[mt][nt][3]);
                float2 x1 = *(const float2*)&X[((size_t)b * MD + r1) * ND + col];
                float2 x2 = *(const float2*)&X[((size_t)b * MD + r2) * ND + col];
                v1.x = v1.x * a_out + x1.x * a_x;  v1.y = v1.y * a_out + x1.y * a_x;
                v2.x = v2.x * a_out + x2.x * a_x;  v2.y = v2.y * a_out + x2.y * a_x;
                *(float2*)&Cb[(size_t)r1 * ND + col] = v1;
                *(float2*)&Cb[(size_t)r2 * ND + col] = v2;
            }
        }
    }
}

// ---------------------------------------------------------------------------
// fp16 flash attention, register-direct P (validated R14). smem 64KB.
// ---------------------------------------------------------------------------
__global__ void __launch_bounds__(256, 2) attn_f16(const __half* __restrict__ qn,
                                                   const __half* __restrict__ kn,
                                                   const __half* __restrict__ vn,
                                                   const __half* __restrict__ km,
                                                   const __half* __restrict__ vm,
                                                   __half* __restrict__ attn_out)
{
    extern __shared__ char smc[];
    const uint32_t sb = (uint32_t)__cvta_generic_to_shared(smc);
    const uint32_t QS = sb, KS = sb + 16384, VS = sb + 40960;

    const int b = blockIdx.z, h = blockIdx.y, i0 = blockIdx.x * 128;
    const int tid = threadIdx.x, lane = tid & 31;
    const int g = lane >> 2, tg = lane & 3;
    const int m0 = (tid >> 5) * 16;
    const int mat = lane >> 3, rr = lane & 7;

    const __half* qh = qn + ((size_t)(b * HEADS + h) * NPIX + i0) * DIMH;
    const __half* kh = kn + (size_t)(b * HEADS + h) * NPIX * DIMH;
    const __half* vh = vn + (size_t)(b * HEADS + h) * NPIX * DIMH;

    int cr[2], cc[2];
    uint32_t coff[2];
#pragma unroll
    for (int i = 0; i < 2; i++) {
        int idx = tid + i * 256;
        cr[i] = idx >> 3;  cc[i] = idx & 7;
        coff[i] = cr[i] * 128 + ((cc[i] ^ (cr[i] & 7)) << 4);
    }

#pragma unroll
    for (int i = 0; i < 2; i++) {
        int sz = (cr[i] < 4) ? 16 : 0;
        cp16z(KS + coff[i], km + ((h * 4 + (cr[i] & 3)) * 64 + cc[i] * 8), sz);
        cp16z(VS + coff[i], vm + ((h * 4 + (cr[i] & 3)) * 64 + cc[i] * 8), sz);
    }
    asm volatile("cp.async.commit_group;");
#pragma unroll
    for (int i = 0; i < 2; i++) {
        cp16(KS + 8192 + coff[i], kh + cr[i] * 64 + cc[i] * 8);
        cp16(VS + 8192 + coff[i], vh + cr[i] * 64 + cc[i] * 8);
    }
    asm volatile("cp.async.commit_group;");

    for (int idx = tid; idx < 1024; idx += 256) {
        int r = idx >> 3, c = idx & 7;
        uint4 v = *(const uint4*)(qh + r * 64 + c * 8);
        *(uint4*)(smc + r * 128 + ((c ^ (r & 7)) << 4)) = v;
    }
    __syncthreads();

    uint32_t aq[4][4];
    {
        int qrow = m0 + (mat & 1) * 8 + rr;
#pragma unroll
        for (int kc = 0; kc < 4; kc++) {
            int ch = 2 * kc + (mat >> 1);
            ldsm_x4(aq[kc][0], aq[kc][1], aq[kc][2], aq[kc][3],
                    QS + qrow * 128 + ((ch ^ (qrow & 7)) << 4));
        }
    }

    float oacc[8][4];
#pragma unroll
    for (int nt = 0; nt < 8; nt++)
#pragma unroll
        for (int r = 0; r < 4; r++) oacc[nt][r] = 0.f;
    float mrow[2] = {-1e30f, -1e30f};
    float lrow[2] = {0.f, 0.f};

    int s_comp = 0, s_issue = 2;
    for (int t = 0; t <= 16; ++t) {
        if (t < 16) asm volatile("cp.async.wait_group 1;");
        else        asm volatile("cp.async.wait_group 0;");
        __syncthreads();

        if (t + 2 <= 16) {
            const __half* kt = kh + (size_t)(t + 1) * 64 * 64;
            const __half* vt = vh + (size_t)(t + 1) * 64 * 64;
            uint32_t kb = KS + s_issue * 8192;
            uint32_t vb = VS + s_issue * 8192;
#pragma unroll
            for (int i = 0; i < 2; i++) {
                cp16(kb + coff[i], kt + cr[i] * 64 + cc[i] * 8);
                cp16(vb + coff[i], vt + cr[i] * 64 + cc[i] * 8);
            }
            asm volatile("cp.async.commit_group;");
            s_issue++; if (s_issue == 3) s_issue = 0;
        }

        const uint32_t kb = KS + s_comp * 8192;
        const uint32_t vb = VS + s_comp * 8192;
        s_comp++; if (s_comp == 3) s_comp = 0;

        float sacc[8][4];
#pragma unroll
        for (int nt = 0; nt < 8; nt++)
#pragma unroll
            for (int r = 0; r < 4; r++) sacc[nt][r] = 0.f;
#pragma unroll
        for (int np = 0; np < 4; np++) {
            int key = (2 * np + (mat >> 1)) * 8 + rr;
#pragma unroll
            for (int kc = 0; kc < 4; kc++) {
                int ch = 2 * kc + (mat & 1);
                uint32_t addr = kb + key * 128 + ((ch ^ (key & 7)) << 4);
                uint32_t b0, b1, b2, b3;
                ldsm_x4(b0, b1, b2, b3, addr);
                mma_f16(sacc[2 * np],     aq[kc][0], aq[kc][1], aq[kc][2], aq[kc][3], b0, b1);
                mma_f16(sacc[2 * np + 1], aq[kc][0], aq[kc][1], aq[kc][2], aq[kc][3], b2, b3);
            }
        }
        if (t == 0) {
#pragma unroll
            for (int nt = 0; nt < 8; nt++) {
                int c0 = nt * 8 + 2 * tg;
                if (c0 >= 4)     { sacc[nt][0] = -1e30f; sacc[nt][2] = -1e30f; }
                if (c0 + 1 >= 4) { sacc[nt][1] = -1e30f; sacc[nt][3] = -1e30f; }
            }
        }

        float tm0 = -1e30f, tm1 = -1e30f;
#pragma unroll
        for (int nt = 0; nt < 8; nt++) {
            tm0 = fmaxf(tm0, fmaxf(sacc[nt][0], sacc[nt][1]));
            tm1 = fmaxf(tm1, fmaxf(sacc[nt][2], sacc[nt][3]));
        }
        tm0 = fmaxf(tm0, __shfl_xor_sync(0xffffffffu, tm0, 1));
        tm0 = fmaxf(tm0, __shfl_xor_sync(0xffffffffu, tm0, 2));
        tm1 = fmaxf(tm1, __shfl_xor_sync(0xffffffffu, tm1, 1));
        tm1 = fmaxf(tm1, __shfl_xor_sync(0xffffffffu, tm1, 2));

        float mn0 = fmaxf(mrow[0], tm0), mn1 = fmaxf(mrow[1], tm1);
        float al0 = ex2f(mrow[0] - mn0), al1 = ex2f(mrow[1] - mn1);
        float rs0 = 0.f, rs1 = 0.f;
        uint32_t pa[8], pb[8];
#pragma unroll
        for (int nt = 0; nt < 8; nt++) {
            float p00 = ex2f(sacc[nt][0] - mn0);
            float p01 = ex2f(sacc[nt][1] - mn0);
            float p10 = ex2f(sacc[nt][2] - mn1);
            float p11 = ex2f(sacc[nt][3] - mn1);
            rs0 += p00 + p01;  rs1 += p10 + p11;
            pa[nt] = packh2(p00, p01);
            pb[nt] = packh2(p10, p11);
        }
        rs0 += __shfl_xor_sync(0xffffffffu, rs0, 1);
        rs0 += __shfl_xor_sync(0xffffffffu, rs0, 2);
        rs1 += __shfl_xor_sync(0xffffffffu, rs1, 1);
        rs1 += __shfl_xor_sync(0xffffffffu, rs1, 2);
        lrow[0] = lrow[0] * al0 + rs0;  mrow[0] = mn0;
        lrow[1] = lrow[1] * al1 + rs1;  mrow[1] = mn1;
#pragma unroll
        for (int nt = 0; nt < 8; nt++) {
            oacc[nt][0] *= al0;  oacc[nt][1] *= al0;
            oacc[nt][2] *= al1;  oacc[nt][3] *= al1;
        }

#pragma unroll
        for (int kc = 0; kc < 4; kc++) {
            uint32_t a0 = pa[2 * kc],     a1 = pb[2 * kc];
            uint32_t a2 = pa[2 * kc + 1], a3 = pb[2 * kc + 1];
            int key = kc * 16 + (mat & 1) * 8 + rr;
#pragma unroll
            for (int np = 0; np < 4; np++) {
                int ch = 2 * np + (mat >> 1);
                uint32_t vaddr = vb + key * 128 + ((ch ^ (key & 7)) << 4);
                uint32_t b0, b1, b2, b3;
                ldsm_x4t(b0, b1, b2, b3, vaddr);
                mma_f16(oacc[2 * np],     a0, a1, a2, a3, b0, b1);
                mma_f16(oacc[2 * np + 1], a0, a1, a2, a3, b2, b3);
            }
        }
    }

    __syncthreads();
    float* fs = (float*)smc;
    {
        float il0 = 1.f / lrow[0], il1 = 1.f / lrow[1];
        const int row0 = m0 + g, row1 = m0 + g + 8;
#pragma unroll
        for (int nt = 0; nt < 8; nt++) {
            int c = nt * 8 + 2 * tg;
            fs[row0 * 66 + c]     = oacc[nt][0] * il0;
            fs[row0 * 66 + c + 1] = oacc[nt][1] * il0;
            fs[row1 * 66 + c]     = oacc[nt][2] * il1;
            fs[row1 * 66 + c + 1] = oacc[nt][3] * il1;
        }
    }
    __syncthreads();
    {
        __half* ob = attn_out + ((size_t)b * HID + h * DIMH) * NPIX;
        for (int idx = tid; idx < 128 * 64; idx += 256) {
            int m = idx & 127, d = idx >> 7;
            ob[(size_t)d * NPIX + i0 + m] = __float2half(fs[m * 66 + d]);
        }
    }
}

// ---------------------------------------------------------------------------
// Launcher: two-stream half-batch pipeline (fork after prep, join at end).
// ---------------------------------------------------------------------------
extern "C" void kernel_launch(void* const* d_in, const int* in_sizes, int n_in,
                              void* d_out, int out_size)
{
    const float* x      = (const float*)d_in[0];  // [16,512,32,32]
    const float* w_qkv  = (const float*)d_in[1];  // [1536,512]
    const float* w_out  = (const float*)d_in[2];  // [512,512]
    const float* mem_kv = (const float*)d_in[3];  // [2,8,4,64]
    float* out = (float*)d_out;                   // [16,512,32,32]

    __half *wnq, *wno, *xh, *attn, *qn, *kn, *vn, *km, *vm;
    cudaGetSymbolAddress((void**)&wnq,  g_wn_qkv);
    cudaGetSymbolAddress((void**)&wno,  g_wn_out);
    cudaGetSymbolAddress((void**)&xh,   g_xh);
    cudaGetSymbolAddress((void**)&attn, g_attn);
    cudaGetSymbolAddress((void**)&qn,   g_qn);
    cudaGetSymbolAddress((void**)&kn,   g_kn);
    cudaGetSymbolAddress((void**)&vn,   g_vn);
    cudaGetSymbolAddress((void**)&km,   g_km);
    cudaGetSymbolAddress((void**)&vm,   g_vm);

    cudaFuncSetAttribute(hgemm_pipe<K3, true>,
                         cudaFuncAttributeMaxDynamicSharedMemorySize, 98304);
    cudaFuncSetAttribute(hgemm_pipe<CIN, false>,
                         cudaFuncAttributeMaxDynamicSharedMemorySize, 98304);
    cudaFuncSetAttribute(attn_f16, cudaFuncAttributeMaxDynamicSharedMemorySize, 65536);

    // per-call stream/event (never destroyed: may be referenced by capture)
    cudaStream_t s1;
    cudaEvent_t e_prep, e_done;
    cudaStreamCreateWithFlags(&s1, cudaStreamNonBlocking);
    cudaEventCreateWithFlags(&e_prep, cudaEventDisableTiming);
    cudaEventCreateWithFlags(&e_done, cudaEventDisableTiming);

    // half-B pointer offsets (batches 8..15)
    const size_t oBCH = (size_t)NBH * CIN * NPIX;             // [b][512][1024] half/float
    const size_t oQKV = (size_t)NBH * HEADS * NPIX * DIMH;    // [b,h,n,d]
    const __half* xh1   = xh + oBCH;
    __half* qn1 = qn + oQKV; __half* kn1 = kn + oQKV; __half* vn1 = vn + oQKV;
    __half* attn1 = attn + oBCH;
    const float* x1 = x + oBCH;
    float* out1 = out + oBCH;

    // prep on legacy stream; fork
    prep_kernel<<<PREP_X + 2048, 256>>>(w_qkv, w_out, mem_kv, x,
                                        wnq, wno, km, vm, xh);
    cudaEventRecord(e_prep, 0);
    cudaStreamWaitEvent(s1, e_prep, 0);

    // half A (batches 0..7) on legacy stream
    hgemm_pipe<K3, true><<<dim3(8, K3 / 128, NBH), 256, 98304>>>(
        wnq, xh, qn, kn, vn, nullptr, nullptr);
    // half B (batches 8..15) on s1
    hgemm_pipe<K3, true><<<dim3(8, K3 / 128, NBH), 256, 98304, s1>>>(
        wnq, xh1, qn1, kn1, vn1, nullptr, nullptr);

    attn_f16<<<dim3(NPIX / 128, HEADS, NBH), 256, 65536>>>(qn, kn, vn, km, vm, attn);
    attn_f16<<<dim3(NPIX / 128, HEADS, NBH), 256, 65536, s1>>>(qn1, kn1, vn1, km, vm, attn1);

    hgemm_pipe<CIN, false><<<dim3(8, CIN / 128, NBH), 256, 98304>>>(
        wno, attn, nullptr, nullptr, nullptr, out, x);
    hgemm_pipe<CIN, false><<<dim3(8, CIN / 128, NBH), 256, 98304, s1>>>(
        wno, attn1, nullptr, nullptr, nullptr, out1, x1);

    // join
    cudaEventRecord(e_done, s1);
    cudaStreamWaitEvent(0, e_done, 0);
}

// round 17
// speedup vs baseline: 1.1844x; 1.0528x over previous
#include <cuda_runtime.h>
#include <cuda_fp16.h>
#include <math.h>
#include <stdint.h>

#define NB    16
#define CIN   512
#define NPIX  1024
#define HEADS 8
#define DIMH  64
#define HID   512
#define K3    1536   // 3*HID
#define NBH   8      // batches per pipeline half

// Scratch (allocation-free, device globals)
__device__ __half g_wn_qkv[K3 * CIN];
__device__ __half g_wn_out[CIN * HID];
__device__ __half g_xh[(size_t)NB * CIN * NPIX];          // fp16 x [b][ch][pix]
__device__ __half g_attn[(size_t)NB * HID * NPIX];
__device__ __half g_qn[(size_t)NB * HEADS * NPIX * DIMH];
__device__ __half g_kn[(size_t)NB * HEADS * NPIX * DIMH];
__device__ __half g_vn[(size_t)NB * HEADS * NPIX * DIMH];
__device__ __half g_km[HEADS * 4 * DIMH];
__device__ __half g_vm[HEADS * 4 * DIMH];

// ---------------------------------------------------------------------------
// helpers
// ---------------------------------------------------------------------------
__device__ __forceinline__ float ex2f(float x) {
    float y;
    asm("ex2.approx.f32 %0, %1;" : "=f"(y) : "f"(x));
    return y;
}
__device__ __forceinline__ void mma_f16(float (&d)[4],
                                        uint32_t a0, uint32_t a1, uint32_t a2, uint32_t a3,
                                        uint32_t b0, uint32_t b1) {
    asm volatile(
        "mma.sync.aligned.m16n8k16.row.col.f32.f16.f16.f32 "
        "{%0,%1,%2,%3}, {%4,%5,%6,%7}, {%8,%9}, {%0,%1,%2,%3};"
        : "+f"(d[0]), "+f"(d[1]), "+f"(d[2]), "+f"(d[3])
        : "r"(a0), "r"(a1), "r"(a2), "r"(a3), "r"(b0), "r"(b1));
}
__device__ __forceinline__ void ldsm_x4(uint32_t& r0, uint32_t& r1, uint32_t& r2,
                                        uint32_t& r3, uint32_t addr) {
    asm volatile("ldmatrix.sync.aligned.m8n8.x4.shared.b16 {%0,%1,%2,%3}, [%4];"
                 : "=r"(r0), "=r"(r1), "=r"(r2), "=r"(r3) : "r"(addr));
}
__device__ __forceinline__ void ldsm_x4t(uint32_t& r0, uint32_t& r1, uint32_t& r2,
                                         uint32_t& r3, uint32_t addr) {
    asm volatile("ldmatrix.sync.aligned.m8n8.x4.trans.shared.b16 {%0,%1,%2,%3}, [%4];"
                 : "=r"(r0), "=r"(r1), "=r"(r2), "=r"(r3) : "r"(addr));
}
__device__ __forceinline__ void cp16(uint32_t s, const void* g) {
    asm volatile("cp.async.cg.shared.global [%0], [%1], 16;" :: "r"(s), "l"(g));
}
__device__ __forceinline__ void cp16z(uint32_t s, const void* g, int sz) {
    asm volatile("cp.async.cg.shared.global [%0], [%1], 16, %2;"
                 :: "r"(s), "l"(g), "r"(sz));
}
__device__ __forceinline__ uint32_t packh2(float a, float b) {
    __half2 h = __floats2half2_rn(a, b);
    return *(uint32_t*)&h;
}

// ---------------------------------------------------------------------------
// prep: weight norms (fan-in 512) + mem_kv norm + x fp32->fp16 (channel-major).
// ---------------------------------------------------------------------------
#define PREP_MEMKV (K3 + CIN)
#define PREP_X     (K3 + CIN + 64)

__global__ void __launch_bounds__(256) prep_kernel(const float* __restrict__ w_qkv,
                                                   const float* __restrict__ w_out,
                                                   const float* __restrict__ mem_kv,
                                                   const float* __restrict__ x,
                                                   __half* __restrict__ wnq,
                                                   __half* __restrict__ wno,
                                                   __half* __restrict__ km,
                                                   __half* __restrict__ vm,
                                                   __half* __restrict__ xh)
{
    int r = blockIdx.x;
    if (r >= PREP_X) {
        size_t base = (size_t)(r - PREP_X) * 4096;
#pragma unroll
        for (int j = 0; j < 2; j++) {
            size_t off = base + ((size_t)j * 256 + threadIdx.x) * 8;
            float4 f0 = *(const float4*)(x + off);
            float4 f1 = *(const float4*)(x + off + 4);
            uint4 pk;
            pk.x = packh2(f0.x, f0.y); pk.y = packh2(f0.z, f0.w);
            pk.z = packh2(f1.x, f1.y); pk.w = packh2(f1.z, f1.w);
            *(uint4*)(xh + off) = pk;
        }
        return;
    }
    if (r >= PREP_MEMKV) {
        if (threadIdx.x < 32) {
            int row = r - PREP_MEMKV;
            int part = row >> 5, rk = row & 31;
            const float* src = mem_kv + part * 2048 + rk * 64;
            float v0 = src[threadIdx.x], v1 = src[threadIdx.x + 32];
            float s = v0 * v0 + v1 * v1;
#pragma unroll
            for (int off = 16; off; off >>= 1) s += __shfl_xor_sync(0xffffffffu, s, off);
            float sc = 8.f / fmaxf(sqrtf(s), 1e-4f);
            __half* dst = (part ? vm : km) + rk * 64;
            dst[threadIdx.x]      = __float2half(v0 * sc);
            dst[threadIdx.x + 32] = __float2half(v1 * sc);
        }
        return;
    }
    const float* wr;
    __half* out;
    if (r < K3) { wr = w_qkv + (size_t)r * CIN;        out = wnq + (size_t)r * CIN; }
    else        { wr = w_out + (size_t)(r - K3) * HID; out = wno + (size_t)(r - K3) * HID; }
    float s = 0.f;
    for (int i = threadIdx.x; i < 512; i += 256) { float v = wr[i]; s += v * v; }
    __shared__ float red[8];
#pragma unroll
    for (int off = 16; off; off >>= 1) s += __shfl_xor_sync(0xffffffffu, s, off);
    if ((threadIdx.x & 31) == 0) red[threadIdx.x >> 5] = s;
    __syncthreads();
    if (threadIdx.x == 0) {
        float v = 0.f;
#pragma unroll
        for (int i = 0; i < 8; i++) v += red[i];
        red[0] = v;
    }
    __syncthreads();
    float inv = 1.f / (1e-4f * 22.627416998f + sqrtf(red[0]));
    for (int i = threadIdx.x; i < 512; i += 256)
        out[i] = __float2half(wr[i] * inv);
}

// ---------------------------------------------------------------------------
// 3-stage cp.async fp16 GEMM (validated R10/R14): C[b](MDx1024)=A(MDx512)*B[b].
// QKV=true : fused pixel-norm epilogue -> qn/kn/vn. QKV=false: MPAdd -> fp32.
// ---------------------------------------------------------------------------
template<int MD, bool QKV>
__global__ void __launch_bounds__(256, 2) hgemm_pipe(const __half* __restrict__ A,
                                                     const __half* __restrict__ Bm,
                                                     __half* __restrict__ qn,
                                                     __half* __restrict__ kn,
                                                     __half* __restrict__ vn,
                                                     float* __restrict__ Cf,
                                                     const float* __restrict__ X)
{
    constexpr int ND = 1024, KD = 512;
    extern __shared__ char smc[];
    const uint32_t sb = (uint32_t)__cvta_generic_to_shared(smc);

    const int b   = blockIdx.z;
    const int bm0 = blockIdx.y * 128;
    const int bn0 = blockIdx.x * 128;
    const __half* Bh = Bm + (size_t)b * KD * ND;

    const int tid = threadIdx.x;
    const int w = tid >> 5, lane = tid & 31;
    const int g = lane >> 2, tg = lane & 3;
    const int mat = lane >> 3, rr = lane & 7;
    const int m_off = (w >> 2) * 64;
    const int n_off = (w & 3) * 32;

    float acc[4][4][4];
#pragma unroll
    for (int i = 0; i < 4; i++)
#pragma unroll
        for (int j = 0; j < 4; j++)
#pragma unroll
            for (int r = 0; r < 4; r++) acc[i][j][r] = 0.f;

    int ar[4], ac[4], br_[4], bc[4];
    uint32_t aoff[4], boff[4];
#pragma unroll
    for (int i = 0; i < 4; i++) {
        int cid = i * 256 + tid;
        ar[i] = cid >> 3;  ac[i] = cid & 7;
        br_[i] = cid >> 4; bc[i] = cid & 15;
        aoff[i] = ar[i] * 128 + ((ac[i] ^ (ar[i] & 7)) << 4);
        boff[i] = 16384 + br_[i] * 256 +
                  (((bc[i] & 8) | ((bc[i] & 7) ^ (br_[i] & 7))) << 4);
    }

#pragma unroll
    for (int s = 0; s < 2; s++) {
        int k0 = s * 64;
        uint32_t st = sb + s * 32768;
#pragma unroll
        for (int i = 0; i < 4; i++) {
            cp16(st + aoff[i], A + (size_t)(bm0 + ar[i]) * KD + k0 + ac[i] * 8);
            cp16(st + boff[i], Bh + (size_t)(k0 + br_[i]) * ND + bn0 + bc[i] * 8);
        }
        asm volatile("cp.async.commit_group;");
    }

    int s_comp = 0, s_issue = 2;
    for (int it = 0; it < 8; ++it) {
        if (it < 7) asm volatile("cp.async.wait_group 1;");
        else        asm volatile("cp.async.wait_group 0;");
        __syncthreads();

        if (it + 2 < 8) {
            int k0 = (it + 2) * 64;
            uint32_t st = sb + s_issue * 32768;
#pragma unroll
            for (int i = 0; i < 4; i++) {
                cp16(st + aoff[i], A + (size_t)(bm0 + ar[i]) * KD + k0 + ac[i] * 8);
                cp16(st + boff[i], Bh + (size_t)(k0 + br_[i]) * ND + bn0 + bc[i] * 8);
            }
            asm volatile("cp.async.commit_group;");
            s_issue++; if (s_issue == 3) s_issue = 0;
        }

        const uint32_t AS = sb + s_comp * 32768;
        const uint32_t BS = AS + 16384;
        s_comp++; if (s_comp == 3) s_comp = 0;
#pragma unroll
        for (int kk = 0; kk < 4; kk++) {
            uint32_t af[4][4];
#pragma unroll
            for (int mt = 0; mt < 4; mt++) {
                int row = m_off + mt * 16 + (mat & 1) * 8 + rr;
                int ch = kk * 2 + (mat >> 1);
                ldsm_x4(af[mt][0], af[mt][1], af[mt][2], af[mt][3],
                        AS + row * 128 + ((ch ^ (row & 7)) << 4));
            }
#pragma unroll
            for (int np = 0; np < 2; np++) {
                int row = kk * 16 + (mat & 1) * 8 + rr;
                int c = (n_off >> 3) + np * 2 + (mat >> 1);
                uint32_t b0, b1, b2, b3;
                ldsm_x4t(b0, b1, b2, b3,
                         BS + row * 256 + (((c & 8) | ((c & 7) ^ (row & 7))) << 4));
#pragma unroll
                for (int mt = 0; mt < 4; mt++) {
                    mma_f16(acc[mt][np * 2],     af[mt][0], af[mt][1], af[mt][2], af[mt][3], b0, b1);
                    mma_f16(acc[mt][np * 2 + 1], af[mt][0], af[mt][1], af[mt][2], af[mt][3], b2, b3);
                }
            }
        }
    }

    if (QKV) {
        __syncthreads();
        const int gr0  = bm0 + m_off;
        const int comp = gr0 >> 9;
        const int head = (gr0 & 511) >> 6;
        const float sc_num = (comp == 0) ? 1.4426950408889634f : 8.f;
        __half* st = (__half*)(smc + w * 4096);

#pragma unroll
        for (int nt = 0; nt < 4; nt++) {
            float ss0 = 0.f, ss1 = 0.f;
#pragma unroll
            for (int mt = 0; mt < 4; mt++) {
                ss0 += acc[mt][nt][0] * acc[mt][nt][0] + acc[mt][nt][2] * acc[mt][nt][2];
                ss1 += acc[mt][nt][1] * acc[mt][nt][1] + acc[mt][nt][3] * acc[mt][nt][3];
            }
#pragma unroll
            for (int off = 4; off <= 16; off <<= 1) {
                ss0 += __shfl_xor_sync(0xffffffffu, ss0, off);
                ss1 += __shfl_xor_sync(0xffffffffu, ss1, off);
            }
            float s0 = sc_num / fmaxf(sqrtf(ss0), 1e-4f);
            float s1 = sc_num / fmaxf(sqrtf(ss1), 1e-4f);
            int c0 = nt * 8 + 2 * tg;
#pragma unroll
            for (int mt = 0; mt < 4; mt++) {
                int r = mt * 16 + g;
                st[c0 * 64 + r]           = __float2half(acc[mt][nt][0] * s0);
                st[c0 * 64 + r + 8]       = __float2half(acc[mt][nt][2] * s0);
                st[(c0 + 1) * 64 + r]     = __float2half(acc[mt][nt][1] * s1);
                st[(c0 + 1) * 64 + r + 8] = __float2half(acc[mt][nt][3] * s1);
            }
        }
        __syncwarp();
        __half* dst = (comp == 0 ? qn : comp == 1 ? kn : vn) +
                      ((size_t)(b * HEADS + head) * NPIX + bn0 + n_off) * DIMH;
#pragma unroll 8
        for (int c = 0; c < 32; c++) {
            __half2 v = *(__half2*)(st + c * 64 + lane * 2);
            *(__half2*)(dst + (size_t)c * DIMH + lane * 2) = v;
        }
    } else {
        const float a_out = 0.9191450300f;  // 0.7 / sqrt(0.58)
        const float a_x   = 0.3939192986f;  // 0.3 / sqrt(0.58)
        float* Cb = Cf + (size_t)b * MD * ND;
#pragma unroll
        for (int mt = 0; mt < 4; mt++) {
            int r1 = bm0 + m_off + mt * 16 + g;
            int r2 = r1 + 8;
#pragma unroll
            for (int nt = 0; nt < 4; nt++) {
                int col = bn0 + n_off + nt * 8 + 2 * tg;
                float2 v1 = make_float2(acc[mt][nt][0], acc[mt][nt][1]);
                float2 v2 = make_float2(acc[mt][nt][2], acc[mt][nt][3]);
                float2 x1 = *(const float2*)&X[((size_t)b * MD + r1) * ND + col];
                float2 x2 = *(const float2*)&X[((size_t)b * MD + r2) * ND + col];
                v1.x = v1.x * a_out + x1.x * a_x;  v1.y = v1.y * a_out + x1.y * a_x;
                v2.x = v2.x * a_out + x2.x * a_x;  v2.y = v2.y * a_out + x2.y * a_x;
                *(float2*)&Cb[(size_t)r1 * ND + col] = v1;
                *(float2*)&Cb[(size_t)r2 * ND + col] = v2;
            }
        }
    }
}

// ---------------------------------------------------------------------------
// fp16 flash attention, FIXED-MAX softmax (C = 8*log2e bounds all scores by
// Cauchy-Schwarz: ||q̂||=log2e, ||k̂||=8), register-direct P. smem 64KB.
// No running max, no accumulator rescale - scores are exp2(s - C) directly.
// ---------------------------------------------------------------------------
#define SMAX_C 11.541560327111707f   // 8 * log2(e)

__global__ void __launch_bounds__(256, 2) attn_f16(const __half* __restrict__ qn,
                                                   const __half* __restrict__ kn,
                                                   const __half* __restrict__ vn,
                                                   const __half* __restrict__ km,
                                                   const __half* __restrict__ vm,
                                                   __half* __restrict__ attn_out)
{
    extern __shared__ char smc[];
    const uint32_t sb = (uint32_t)__cvta_generic_to_shared(smc);
    const uint32_t QS = sb, KS = sb + 16384, VS = sb + 40960;

    const int b = blockIdx.z, h = blockIdx.y, i0 = blockIdx.x * 128;
    const int tid = threadIdx.x, lane = tid & 31;
    const int g = lane >> 2, tg = lane & 3;
    const int m0 = (tid >> 5) * 16;
    const int mat = lane >> 3, rr = lane & 7;

    const __half* qh = qn + ((size_t)(b * HEADS + h) * NPIX + i0) * DIMH;
    const __half* kh = kn + (size_t)(b * HEADS + h) * NPIX * DIMH;
    const __half* vh = vn + (size_t)(b * HEADS + h) * NPIX * DIMH;

    int cr[2], cc[2];
    uint32_t coff[2];
#pragma unroll
    for (int i = 0; i < 2; i++) {
        int idx = tid + i * 256;
        cr[i] = idx >> 3;  cc[i] = idx & 7;
        coff[i] = cr[i] * 128 + ((cc[i] ^ (cr[i] & 7)) << 4);
    }

#pragma unroll
    for (int i = 0; i < 2; i++) {
        int sz = (cr[i] < 4) ? 16 : 0;
        cp16z(KS + coff[i], km + ((h * 4 + (cr[i] & 3)) * 64 + cc[i] * 8), sz);
        cp16z(VS + coff[i], vm + ((h * 4 + (cr[i] & 3)) * 64 + cc[i] * 8), sz);
    }
    asm volatile("cp.async.commit_group;");
#pragma unroll
    for (int i = 0; i < 2; i++) {
        cp16(KS + 8192 + coff[i], kh + cr[i] * 64 + cc[i] * 8);
        cp16(VS + 8192 + coff[i], vh + cr[i] * 64 + cc[i] * 8);
    }
    asm volatile("cp.async.commit_group;");

    for (int idx = tid; idx < 1024; idx += 256) {
        int r = idx >> 3, c = idx & 7;
        uint4 v = *(const uint4*)(qh + r * 64 + c * 8);
        *(uint4*)(smc + r * 128 + ((c ^ (r & 7)) << 4)) = v;
    }
    __syncthreads();

    uint32_t aq[4][4];
    {
        int qrow = m0 + (mat & 1) * 8 + rr;
#pragma unroll
        for (int kc = 0; kc < 4; kc++) {
            int ch = 2 * kc + (mat >> 1);
            ldsm_x4(aq[kc][0], aq[kc][1], aq[kc][2], aq[kc][3],
                    QS + qrow * 128 + ((ch ^ (qrow & 7)) << 4));
        }
    }

    float oacc[8][4];
#pragma unroll
    for (int nt = 0; nt < 8; nt++)
#pragma unroll
        for (int r = 0; r < 4; r++) oacc[nt][r] = 0.f;
    float lrow[2] = {0.f, 0.f};

    int s_comp = 0, s_issue = 2;
    for (int t = 0; t <= 16; ++t) {
        if (t < 16) asm volatile("cp.async.wait_group 1;");
        else        asm volatile("cp.async.wait_group 0;");
        __syncthreads();

        if (t + 2 <= 16) {
            const __half* kt = kh + (size_t)(t + 1) * 64 * 64;
            const __half* vt = vh + (size_t)(t + 1) * 64 * 64;
            uint32_t kb = KS + s_issue * 8192;
            uint32_t vb = VS + s_issue * 8192;
#pragma unroll
            for (int i = 0; i < 2; i++) {
                cp16(kb + coff[i], kt + cr[i] * 64 + cc[i] * 8);
                cp16(vb + coff[i], vt + cr[i] * 64 + cc[i] * 8);
            }
            asm volatile("cp.async.commit_group;");
            s_issue++; if (s_issue == 3) s_issue = 0;
        }

        const uint32_t kb = KS + s_comp * 8192;
        const uint32_t vb = VS + s_comp * 8192;
        s_comp++; if (s_comp == 3) s_comp = 0;

        // ---- S = Q.K^T
        float sacc[8][4];
#pragma unroll
        for (int nt = 0; nt < 8; nt++)
#pragma unroll
            for (int r = 0; r < 4; r++) sacc[nt][r] = 0.f;
#pragma unroll
        for (int np = 0; np < 4; np++) {
            int key = (2 * np + (mat >> 1)) * 8 + rr;
#pragma unroll
            for (int kc = 0; kc < 4; kc++) {
                int ch = 2 * kc + (mat & 1);
                uint32_t addr = kb + key * 128 + ((ch ^ (key & 7)) << 4);
                uint32_t b0, b1, b2, b3;
                ldsm_x4(b0, b1, b2, b3, addr);
                mma_f16(sacc[2 * np],     aq[kc][0], aq[kc][1], aq[kc][2], aq[kc][3], b0, b1);
                mma_f16(sacc[2 * np + 1], aq[kc][0], aq[kc][1], aq[kc][2], aq[kc][3], b2, b3);
            }
        }
        if (t == 0) {
#pragma unroll
            for (int nt = 0; nt < 8; nt++) {
                int c0 = nt * 8 + 2 * tg;
                if (c0 >= 4)     { sacc[nt][0] = -1e30f; sacc[nt][2] = -1e30f; }
                if (c0 + 1 >= 4) { sacc[nt][1] = -1e30f; sacc[nt][3] = -1e30f; }
            }
        }

        // ---- fixed-max softmax: p = exp2(s - C), pack into PV A-fragments
        float rs0 = 0.f, rs1 = 0.f;
        uint32_t pa[8], pb[8];
#pragma unroll
        for (int nt = 0; nt < 8; nt++) {
            float p00 = ex2f(sacc[nt][0] - SMAX_C);
            float p01 = ex2f(sacc[nt][1] - SMAX_C);
            float p10 = ex2f(sacc[nt][2] - SMAX_C);
            float p11 = ex2f(sacc[nt][3] - SMAX_C);
            rs0 += p00 + p01;  rs1 += p10 + p11;
            pa[nt] = packh2(p00, p01);
            pb[nt] = packh2(p10, p11);
        }
        lrow[0] += rs0;
        lrow[1] += rs1;

        // ---- O += P.V
#pragma unroll
        for (int kc = 0; kc < 4; kc++) {
            uint32_t a0 = pa[2 * kc],     a1 = pb[2 * kc];
            uint32_t a2 = pa[2 * kc + 1], a3 = pb[2 * kc + 1];
            int key = kc * 16 + (mat & 1) * 8 + rr;
#pragma unroll
            for (int np = 0; np < 4; np++) {
                int ch = 2 * np + (mat >> 1);
                uint32_t vaddr = vb + key * 128 + ((ch ^ (key & 7)) << 4);
                uint32_t b0, b1, b2, b3;
                ldsm_x4t(b0, b1, b2, b3, vaddr);
                mma_f16(oacc[2 * np],     a0, a1, a2, a3, b0, b1);
                mma_f16(oacc[2 * np + 1], a0, a1, a2, a3, b2, b3);
            }
        }
    }

    // lane-group sum for l (deferred from per-tile: sums are associative)
    lrow[0] += __shfl_xor_sync(0xffffffffu, lrow[0], 1);
    lrow[0] += __shfl_xor_sync(0xffffffffu, lrow[0], 2);
    lrow[1] += __shfl_xor_sync(0xffffffffu, lrow[1], 1);
    lrow[1] += __shfl_xor_sync(0xffffffffu, lrow[1], 2);

    __syncthreads();
    float* fs = (float*)smc;
    {
        float il0 = 1.f / lrow[0], il1 = 1.f / lrow[1];
        const int row0 = m0 + g, row1 = m0 + g + 8;
#pragma unroll
        for (int nt = 0; nt < 8; nt++) {
            int c = nt * 8 + 2 * tg;
            fs[row0 * 66 + c]     = oacc[nt][0] * il0;
            fs[row0 * 66 + c + 1] = oacc[nt][1] * il0;
            fs[row1 * 66 + c]     = oacc[nt][2] * il1;
            fs[row1 * 66 + c + 1] = oacc[nt][3] * il1;
        }
    }
    __syncthreads();
    {
        __half* ob = attn_out + ((size_t)b * HID + h * DIMH) * NPIX;
        for (int idx = tid; idx < 128 * 64; idx += 256) {
            int m = idx & 127, d = idx >> 7;
            ob[(size_t)d * NPIX + i0 + m] = __float2half(fs[m * 66 + d]);
        }
    }
}

// ---------------------------------------------------------------------------
// Launcher: two-stream half-batch pipeline (validated R16).
// ---------------------------------------------------------------------------
extern "C" void kernel_launch(void* const* d_in, const int* in_sizes, int n_in,
                              void* d_out, int out_size)
{
    const float* x      = (const float*)d_in[0];  // [16,512,32,32]
    const float* w_qkv  = (const float*)d_in[1];  // [1536,512]
    const float* w_out  = (const float*)d_in[2];  // [512,512]
    const float* mem_kv = (const float*)d_in[3];  // [2,8,4,64]
    float* out = (float*)d_out;                   // [16,512,32,32]

    __half *wnq, *wno, *xh, *attn, *qn, *kn, *vn, *km, *vm;
    cudaGetSymbolAddress((void**)&wnq,  g_wn_qkv);
    cudaGetSymbolAddress((void**)&wno,  g_wn_out);
    cudaGetSymbolAddress((void**)&xh,   g_xh);
    cudaGetSymbolAddress((void**)&attn, g_attn);
    cudaGetSymbolAddress((void**)&qn,   g_qn);
    cudaGetSymbolAddress((void**)&kn,   g_kn);
    cudaGetSymbolAddress((void**)&vn,   g_vn);
    cudaGetSymbolAddress((void**)&km,   g_km);
    cudaGetSymbolAddress((void**)&vm,   g_vm);

    cudaFuncSetAttribute(hgemm_pipe<K3, true>,
                         cudaFuncAttributeMaxDynamicSharedMemorySize, 98304);
    cudaFuncSetAttribute(hgemm_pipe<CIN, false>,
                         cudaFuncAttributeMaxDynamicSharedMemorySize, 98304);
    cudaFuncSetAttribute(attn_f16, cudaFuncAttributeMaxDynamicSharedMemorySize, 65536);

    // per-call stream/event (never destroyed: may be referenced by capture)
    cudaStream_t s1;
    cudaEvent_t e_prep, e_done;
    cudaStreamCreateWithFlags(&s1, cudaStreamNonBlocking);
    cudaEventCreateWithFlags(&e_prep, cudaEventDisableTiming);
    cudaEventCreateWithFlags(&e_done, cudaEventDisableTiming);

    const size_t oBCH = (size_t)NBH * CIN * NPIX;
    const size_t oQKV = (size_t)NBH * HEADS * NPIX * DIMH;
    const __half* xh1   = xh + oBCH;
    __half* qn1 = qn + oQKV; __half* kn1 = kn + oQKV; __half* vn1 = vn + oQKV;
    __half* attn1 = attn + oBCH;
    const float* x1 = x + oBCH;
    float* out1 = out + oBCH;

    prep_kernel<<<PREP_X + 2048, 256>>>(w_qkv, w_out, mem_kv, x,
                                        wnq, wno, km, vm, xh);
    cudaEventRecord(e_prep, 0);
    cudaStreamWaitEvent(s1, e_prep, 0);

    hgemm_pipe<K3, true><<<dim3(8, K3 / 128, NBH), 256, 98304>>>(
        wnq, xh, qn, kn, vn, nullptr, nullptr);
    hgemm_pipe<K3, true><<<dim3(8, K3 / 128, NBH), 256, 98304, s1>>>(
        wnq, xh1, qn1, kn1, vn1, nullptr, nullptr);

    attn_f16<<<dim3(NPIX / 128, HEADS, NBH), 256, 65536>>>(qn, kn, vn, km, vm, attn);
    attn_f16<<<dim3(NPIX / 128, HEADS, NBH), 256, 65536, s1>>>(qn1, kn1, vn1, km, vm, attn1);

    hgemm_pipe<CIN, false><<<dim3(8, CIN / 128, NBH), 256, 98304>>>(
        wno, attn, nullptr, nullptr, nullptr, out, x);
    hgemm_pipe<CIN, false><<<dim3(8, CIN / 128, NBH), 256, 98304, s1>>>(
        wno, attn1, nullptr, nullptr, nullptr, out1, x1);

    cudaEventRecord(e_done, s1);
    cudaStreamWaitEvent(0, e_done, 0);
}